// round 4
// baseline (speedup 1.0000x reference)
#include <cuda_runtime.h>
#include <math.h>
#include <stddef.h>

// Problem constants
#define BB   64
#define SS   2048
#define JJ   25
#define HID  256
#define OUTD 128
#define KDIM 264      // compacted input dim: 75 p + 75 vel + 75 acc + 39 angles
#define TILE_M 64
#define NTHR 256

// Prepass outputs: folded W1 (BN scale + joint weights + compaction) and bias
__device__ float g_W1c[KDIM * HID];
__device__ float g_b1c[HID];

__constant__ int c_conn[13][2] = {
    {0,1},{1,5},{1,6},{5,7},{7,9},{6,8},{8,10},
    {1,11},{1,12},{11,13},{13,15},{12,14},{14,16}};

// ---------------------------------------------------------------------------
// Prepass: W1c[k][h] = W1[k_orig][h] * gamma/sqrt(var+eps) * jw(k)
//          b1c[h]    = (b1[h]-mean[h])*g' + beta[h]
// Compact k layout: [p(75), vel(75), acc(75), ang(39)]
// Original k_orig per joint j: [p(3) vel(3) acc(3) ang(3)] -> j*12 + sect*3 + d
// ---------------------------------------------------------------------------
__global__ void prep_kernel(const float* __restrict__ W1, const float* __restrict__ b1,
                            const float* __restrict__ gamma, const float* __restrict__ beta,
                            const float* __restrict__ mean, const float* __restrict__ var,
                            const float* __restrict__ jw) {
    int h = threadIdx.x;
    int k = blockIdx.x;
    float g = gamma[h] * rsqrtf(var[h] + 1e-5f);
    int korig, jidx;
    if (k < 225) {
        int sect = k / 75;
        int r = k % 75;
        jidx = r / 3;
        int d = r % 3;
        korig = jidx * 12 + sect * 3 + d;
    } else {
        int a = k - 225;
        int c = a / 3;
        int d = a % 3;
        jidx = c;
        korig = c * 12 + 9 + d;
    }
    g_W1c[k * HID + h] = W1[korig * HID + h] * g * jw[jidx];
    if (k == 0) g_b1c[h] = (b1[h] - mean[h]) * g + beta[h];
}

// ---------------------------------------------------------------------------
// Fused kernel: one block = 64 consecutive frames of one batch sequence.
// smem layout (floats):
//   [0, 16896)          featT[264][64]  (reused as hiddenS[64][256] after GEMM1)
//   [16896, 20992)      wbuf: double-buffered weight tiles (2 x 2048)
//   [20992, 26008)      pn[66][76]: normalized poses (64 frames + 2 halo)
// Total 26008 floats = 104032 B -> 2 CTAs/SM
// ---------------------------------------------------------------------------
__global__ void __launch_bounds__(NTHR, 2)
fused_kernel(const float* __restrict__ poses,
             const float* __restrict__ W2, const float* __restrict__ b2,
             float* __restrict__ out) {
    extern __shared__ float smem[];
    float* featT = smem;                 // 264*64
    float* wbuf  = smem + 16896;         // 4096
    float* pn    = smem + 16896 + 4096;  // 66*76

    const int tid = threadIdx.x;
    const int rowbase = blockIdx.x * TILE_M;      // == b*S + s0
    const int s0 = (blockIdx.x & 31) * TILE_M;
    const int b  = blockIdx.x >> 5;

    // ---- Stage 1: root-center + max-dist normalize 66 frames ----
    if (tid < 66) {
        int s = s0 - 2 + tid;
        float* dst = pn + tid * 76;
        if (s < 0) {
            #pragma unroll 5
            for (int i = 0; i < 75; i++) dst[i] = 0.0f;
        } else {
            const float* src = poses + ((size_t)b * SS + s) * (JJ * 3);
            float rx = src[0], ry = src[1], rz = src[2];
            float mx = 0.0f;
            for (int j = 0; j < JJ; j++) {
                float dx = src[j*3+0] - rx;
                float dy = src[j*3+1] - ry;
                float dz = src[j*3+2] - rz;
                dst[j*3+0] = dx; dst[j*3+1] = dy; dst[j*3+2] = dz;
                mx = fmaxf(mx, sqrtf(dx*dx + dy*dy + dz*dz));
            }
            float inv = 1.0f / (mx + 1e-8f);
            #pragma unroll 5
            for (int i = 0; i < 75; i++) dst[i] *= inv;
        }
    }
    __syncthreads();

    // ---- Stage 2: build featT[264][64] ----
    if (tid < TILE_M) {
        const int m = tid;
        const int s = s0 + m;
        const float* P   = pn + (m + 2) * 76;
        const float* Pm1 = pn + (m + 1) * 76;
        const float* Pm2 = pn + (m + 0) * 76;
        const bool has1 = (s >= 1), has2 = (s >= 2);
        for (int i = 0; i < 75; i++) {
            float p   = P[i];
            float v   = has1 ? (p - Pm1[i]) : 0.0f;
            float vm1 = has2 ? (Pm1[i] - Pm2[i]) : 0.0f;
            float a   = has1 ? (v - vm1) : 0.0f;
            featT[i * 64 + m]         = p;
            featT[(75 + i) * 64 + m]  = v;
            featT[(150 + i) * 64 + m] = a;
        }
        #pragma unroll
        for (int c = 0; c < 13; c++) {
            int i0 = c_conn[c][0] * 3, i1 = c_conn[c][1] * 3;
            float vx = P[i1+0] - P[i0+0];
            float vy = P[i1+1] - P[i0+1];
            float vz = P[i1+2] - P[i0+2];
            float n = fmaxf(sqrtf(vx*vx + vy*vy + vz*vz), 1e-12f);
            float invn = 1.0f / n;
            featT[(225 + c*3 + 0) * 64 + m] = acosf(fminf(fmaxf(vx*invn, -1.0f), 1.0f));
            featT[(225 + c*3 + 1) * 64 + m] = acosf(fminf(fmaxf(vy*invn, -1.0f), 1.0f));
            featT[(225 + c*3 + 2) * 64 + m] = acosf(fminf(fmaxf(vz*invn, -1.0f), 1.0f));
        }
    }
    __syncthreads();

    // ---- Stage 3: GEMM1  hidden[64][256] = relu(featT^T @ W1c + b1c) ----
    // 256 threads: hg = tid&31 -> 8 h-cols, mg = tid>>5 -> 8 m-rows
    const int hg = tid & 31;
    const int mg = tid >> 5;
    float acc[8][8];
    #pragma unroll
    for (int i = 0; i < 8; i++)
        #pragma unroll
        for (int j = 0; j < 8; j++) acc[i][j] = 0.0f;

    {
        const float4* w1g = reinterpret_cast<const float4*>(g_W1c);
        float4* wb4 = reinterpret_cast<float4*>(wbuf);
        // preload tile 0 (8x256 floats = 512 float4)
        float4 r0 = w1g[tid], r1 = w1g[tid + 256];
        wb4[tid] = r0; wb4[tid + 256] = r1;
        __syncthreads();

        for (int kt = 0; kt < 33; kt++) {
            const int cur = kt & 1;
            if (kt < 32) {
                r0 = w1g[(kt + 1) * 512 + tid];
                r1 = w1g[(kt + 1) * 512 + tid + 256];
            }
            const float* wrow = wbuf + cur * 2048 + hg * 8;
            const float* frow = featT + (kt * 8) * 64 + mg * 8;
            #pragma unroll
            for (int kk = 0; kk < 8; kk++) {
                float4 a0 = *reinterpret_cast<const float4*>(frow + kk * 64);
                float4 a1 = *reinterpret_cast<const float4*>(frow + kk * 64 + 4);
                float4 w0 = *reinterpret_cast<const float4*>(wrow + kk * 256);
                float4 w1v = *reinterpret_cast<const float4*>(wrow + kk * 256 + 4);
                float a[8] = {a0.x, a0.y, a0.z, a0.w, a1.x, a1.y, a1.z, a1.w};
                float w[8] = {w0.x, w0.y, w0.z, w0.w, w1v.x, w1v.y, w1v.z, w1v.w};
                #pragma unroll
                for (int i = 0; i < 8; i++)
                    #pragma unroll
                    for (int j = 0; j < 8; j++)
                        acc[i][j] = fmaf(a[i], w[j], acc[i][j]);
            }
            if (kt < 32) {
                wb4[(cur ^ 1) * 512 + tid] = r0;
                wb4[(cur ^ 1) * 512 + 256 + tid] = r1;
                __syncthreads();
            }
        }
    }
    __syncthreads();   // all featT reads done before overwriting with hiddenS

    // ---- Epilogue 1: bias + relu -> hiddenS[m][h] (row-major, reuse featT) ----
    float* hiddenS = featT;
    {
        float bias[8];
        #pragma unroll
        for (int j = 0; j < 8; j++) bias[j] = g_b1c[hg * 8 + j];
        #pragma unroll
        for (int i = 0; i < 8; i++) {
            float4 v0, v1;
            v0.x = fmaxf(acc[i][0] + bias[0], 0.0f);
            v0.y = fmaxf(acc[i][1] + bias[1], 0.0f);
            v0.z = fmaxf(acc[i][2] + bias[2], 0.0f);
            v0.w = fmaxf(acc[i][3] + bias[3], 0.0f);
            v1.x = fmaxf(acc[i][4] + bias[4], 0.0f);
            v1.y = fmaxf(acc[i][5] + bias[5], 0.0f);
            v1.z = fmaxf(acc[i][6] + bias[6], 0.0f);
            v1.w = fmaxf(acc[i][7] + bias[7], 0.0f);
            float* dst = hiddenS + (mg * 8 + i) * 256 + hg * 8;
            *reinterpret_cast<float4*>(dst)     = v0;
            *reinterpret_cast<float4*>(dst + 4) = v1;
        }
    }
    __syncthreads();

    // ---- Stage 4: GEMM2  out[64][128] = hidden @ W2 + b2 ----
    // og = tid&31 -> 4 o-cols, mg2 = tid>>5 -> 8 m-rows
    const int og = tid & 31;
    const int mg2 = tid >> 5;
    float acc2[8][4];
    #pragma unroll
    for (int i = 0; i < 8; i++)
        #pragma unroll
        for (int j = 0; j < 4; j++) acc2[i][j] = 0.0f;

    {
        const float4* w2g = reinterpret_cast<const float4*>(W2);  // [256][32] f4
        float4* wb4 = reinterpret_cast<float4*>(wbuf);
        float4 q = w2g[tid];          // tile 0: 8x128 = 256 f4
        wb4[tid] = q;
        __syncthreads();

        const float* hrow = hiddenS + mg2 * 8 * 256;
        for (int kt = 0; kt < 32; kt++) {
            const int cur = kt & 1;
            if (kt < 31) q = w2g[(kt + 1) * 256 + tid];
            const float* wrow = wbuf + cur * 1024 + og * 4;
            #pragma unroll
            for (int kk = 0; kk < 8; kk++) {
                const int k2 = kt * 8 + kk;
                float4 wv = *reinterpret_cast<const float4*>(wrow + kk * 128);
                #pragma unroll
                for (int i = 0; i < 8; i++) {
                    float hv = hrow[i * 256 + k2];
                    acc2[i][0] = fmaf(hv, wv.x, acc2[i][0]);
                    acc2[i][1] = fmaf(hv, wv.y, acc2[i][1]);
                    acc2[i][2] = fmaf(hv, wv.z, acc2[i][2]);
                    acc2[i][3] = fmaf(hv, wv.w, acc2[i][3]);
                }
            }
            if (kt < 31) {
                wb4[(cur ^ 1) * 256 + tid] = q;
                __syncthreads();
            }
        }
    }

    // ---- Epilogue 2: + b2, store ----
    {
        float4 bv = *reinterpret_cast<const float4*>(b2 + og * 4);
        #pragma unroll
        for (int i = 0; i < 8; i++) {
            int row = rowbase + mg2 * 8 + i;
            float4 o;
            o.x = acc2[i][0] + bv.x;
            o.y = acc2[i][1] + bv.y;
            o.z = acc2[i][2] + bv.z;
            o.w = acc2[i][3] + bv.w;
            *reinterpret_cast<float4*>(out + (size_t)row * OUTD + og * 4) = o;
        }
    }
}

// ---------------------------------------------------------------------------
extern "C" void kernel_launch(void* const* d_in, const int* in_sizes, int n_in,
                              void* d_out, int out_size) {
    const float* poses = (const float*)d_in[0];
    const float* W1    = (const float*)d_in[1];
    const float* b1    = (const float*)d_in[2];
    const float* gamma = (const float*)d_in[3];
    const float* beta  = (const float*)d_in[4];
    const float* rmean = (const float*)d_in[5];
    const float* rvar  = (const float*)d_in[6];
    const float* W2    = (const float*)d_in[7];
    const float* b2    = (const float*)d_in[8];
    const float* jw    = (const float*)d_in[9];
    float* out = (float*)d_out;

    const int smem_bytes = 26008 * sizeof(float);  // 104032 B
    cudaFuncSetAttribute(fused_kernel, cudaFuncAttributeMaxDynamicSharedMemorySize,
                         smem_bytes);

    prep_kernel<<<KDIM, HID>>>(W1, b1, gamma, beta, rmean, rvar, jw);
    fused_kernel<<<(BB * SS) / TILE_M, NTHR, smem_bytes>>>(poses, W2, b2, out);
}

// round 5
// speedup vs baseline: 1.0440x; 1.0440x over previous
#include <cuda_runtime.h>
#include <math.h>
#include <stddef.h>

// Problem constants
#define BB   64
#define SS   2048
#define JJ   25
#define HID  256
#define OUTD 128
#define KDIM 264      // compacted input dim: 75 p + 75 vel + 75 acc + 39 angles
#define TILE_M 64
#define NTHR 256
#define PNS  77       // padded pn row stride (coprime with 32 banks)

typedef unsigned long long u64;

// Prepass outputs: folded W1 (BN scale + joint weights + compaction) and bias
__device__ __align__(16) float g_W1c[KDIM * HID];
__device__ __align__(16) float g_b1c[HID];

__constant__ int c_conn[13][2] = {
    {0,1},{1,5},{1,6},{5,7},{7,9},{6,8},{8,10},
    {1,11},{1,12},{11,13},{13,15},{12,14},{14,16}};

// ---- packed f32x2 helpers (sm_103a FFMA2 path; ptxas never auto-fuses) ----
__device__ __forceinline__ u64 dup2(float x) {
    u64 r; unsigned u = __float_as_uint(x);
    asm("mov.b64 %0, {%1, %1};" : "=l"(r) : "r"(u));
    return r;
}
__device__ __forceinline__ u64 ffma2(u64 a, u64 b, u64 c) {
    u64 d;
    asm("fma.rn.f32x2 %0, %1, %2, %3;" : "=l"(d) : "l"(a), "l"(b), "l"(c));
    return d;
}
__device__ __forceinline__ u64 add2(u64 a, u64 b) {
    u64 d;
    asm("add.rn.f32x2 %0, %1, %2;" : "=l"(d) : "l"(a), "l"(b));
    return d;
}
__device__ __forceinline__ float2 unpack2(u64 a) {
    unsigned lo, hi;
    asm("mov.b64 {%0, %1}, %2;" : "=r"(lo), "=r"(hi) : "l"(a));
    float2 f; f.x = __uint_as_float(lo); f.y = __uint_as_float(hi);
    return f;
}

// ---------------------------------------------------------------------------
// Prepass: W1c[k][h] = W1[k_orig][h] * gamma/sqrt(var+eps) * jw(k)
//          b1c[h]    = (b1[h]-mean[h])*g' + beta[h]
// ---------------------------------------------------------------------------
__global__ void prep_kernel(const float* __restrict__ W1, const float* __restrict__ b1,
                            const float* __restrict__ gamma, const float* __restrict__ beta,
                            const float* __restrict__ mean, const float* __restrict__ var,
                            const float* __restrict__ jw) {
    int h = threadIdx.x;
    int k = blockIdx.x;
    float g = gamma[h] * rsqrtf(var[h] + 1e-5f);
    int korig, jidx;
    if (k < 225) {
        int sect = k / 75;
        int r = k % 75;
        jidx = r / 3;
        int d = r % 3;
        korig = jidx * 12 + sect * 3 + d;
    } else {
        int a = k - 225;
        int c = a / 3;
        int d = a % 3;
        jidx = c;
        korig = c * 12 + 9 + d;
    }
    g_W1c[k * HID + h] = W1[korig * HID + h] * g * jw[jidx];
    if (k == 0) g_b1c[h] = (b1[h] - mean[h]) * g + beta[h];
}

// ---------------------------------------------------------------------------
// Fused kernel: one block = 64 consecutive frames of one batch sequence.
// smem (floats):
//   [0, 16896)           featT[264][64]   (reused as hiddenS[64][256])
//   [16896, 20992)       wbuf: double-buffered weight tiles (2 x 2048)
//   [20992, 26074)       pn[66][77]: normalized poses (padded stride 77)
// Total 26074 floats = 104296 B -> 2 CTAs/SM
// ---------------------------------------------------------------------------
__global__ void __launch_bounds__(NTHR, 2)
fused_kernel(const float* __restrict__ poses,
             const float* __restrict__ W2, const float* __restrict__ b2,
             float* __restrict__ out) {
    extern __shared__ float smem[];
    float* featT = smem;                 // 264*64
    float* wbuf  = smem + 16896;         // 4096
    float* pn    = smem + 16896 + 4096;  // 66*77

    const int tid = threadIdx.x;
    const int rowbase = blockIdx.x * TILE_M;      // == b*S + s0
    const int s0 = (blockIdx.x & 31) * TILE_M;
    const int b  = blockIdx.x >> 5;

    // ---- Stage 1: root-center + max-dist normalize 66 frames ----
    if (tid < 66) {
        int s = s0 - 2 + tid;
        float* dst = pn + tid * PNS;
        if (s < 0) {
            #pragma unroll 5
            for (int i = 0; i < 75; i++) dst[i] = 0.0f;
        } else {
            const float* src = poses + ((size_t)b * SS + s) * (JJ * 3);
            float rx = src[0], ry = src[1], rz = src[2];
            float mx = 0.0f;
            for (int j = 0; j < JJ; j++) {
                float dx = src[j*3+0] - rx;
                float dy = src[j*3+1] - ry;
                float dz = src[j*3+2] - rz;
                dst[j*3+0] = dx; dst[j*3+1] = dy; dst[j*3+2] = dz;
                mx = fmaxf(mx, sqrtf(dx*dx + dy*dy + dz*dz));
            }
            float inv = 1.0f / (mx + 1e-8f);
            #pragma unroll 5
            for (int i = 0; i < 75; i++) dst[i] *= inv;
        }
    }
    __syncthreads();

    // ---- Stage 2: build featT[264][64] (all 256 threads: 4 groups per frame) ----
    {
        const int m = tid & 63;
        const int g = tid >> 6;      // 0..3
        const int s = s0 + m;
        const float* P   = pn + (m + 2) * PNS;
        const float* Pm1 = pn + (m + 1) * PNS;
        const float* Pm2 = pn + (m + 0) * PNS;
        const bool has1 = (s >= 1), has2 = (s >= 2);
        for (int i = g; i < 75; i += 4) {
            float p   = P[i];
            float v   = has1 ? (p - Pm1[i]) : 0.0f;
            float vm1 = has2 ? (Pm1[i] - Pm2[i]) : 0.0f;
            float a   = has1 ? (v - vm1) : 0.0f;
            featT[i * 64 + m]         = p;
            featT[(75 + i) * 64 + m]  = v;
            featT[(150 + i) * 64 + m] = a;
        }
        for (int c = g; c < 13; c += 4) {
            int i0 = c_conn[c][0] * 3, i1 = c_conn[c][1] * 3;
            float vx = P[i1+0] - P[i0+0];
            float vy = P[i1+1] - P[i0+1];
            float vz = P[i1+2] - P[i0+2];
            float n = fmaxf(sqrtf(vx*vx + vy*vy + vz*vz), 1e-12f);
            float invn = 1.0f / n;
            featT[(225 + c*3 + 0) * 64 + m] = acosf(fminf(fmaxf(vx*invn, -1.0f), 1.0f));
            featT[(225 + c*3 + 1) * 64 + m] = acosf(fminf(fmaxf(vy*invn, -1.0f), 1.0f));
            featT[(225 + c*3 + 2) * 64 + m] = acosf(fminf(fmaxf(vz*invn, -1.0f), 1.0f));
        }
    }
    __syncthreads();

    // ---- Stage 3: GEMM1  hidden[64][256] = relu(featT^T @ W1c + b1c) ----
    // Warp-local 4m x 8h footprint: minimizes distinct LDS bytes per warp.
    const int lane = tid & 31;
    const int wrp  = tid >> 5;
    const int hg = (wrp & 3) * 8 + (lane & 7);   // 0..31 (8 h-cols each)
    const int mg = (wrp >> 2) * 4 + (lane >> 3); // 0..7  (8 m-rows each)

    u64 acc[8][4];
    #pragma unroll
    for (int i = 0; i < 8; i++)
        #pragma unroll
        for (int j = 0; j < 4; j++) acc[i][j] = 0ULL;

    {
        const float4* w1g = reinterpret_cast<const float4*>(g_W1c);
        float4* wb4 = reinterpret_cast<float4*>(wbuf);
        // preload tile 0 (8x256 floats = 512 float4)
        float4 r0 = w1g[tid], r1 = w1g[tid + 256];
        wb4[tid] = r0; wb4[tid + 256] = r1;
        __syncthreads();

        for (int kt = 0; kt < 33; kt++) {
            const int cur = kt & 1;
            if (kt < 32) {
                r0 = w1g[(kt + 1) * 512 + tid];
                r1 = w1g[(kt + 1) * 512 + tid + 256];
            }
            const float* wrow = wbuf + cur * 2048 + hg * 8;
            const float* frow = featT + (kt * 8) * 64 + mg * 8;
            #pragma unroll
            for (int kk = 0; kk < 8; kk++) {
                float4 a0 = *reinterpret_cast<const float4*>(frow + kk * 64);
                float4 a1 = *reinterpret_cast<const float4*>(frow + kk * 64 + 4);
                ulonglong2 wA = *reinterpret_cast<const ulonglong2*>(wrow + kk * 256);
                ulonglong2 wB = *reinterpret_cast<const ulonglong2*>(wrow + kk * 256 + 4);
                float a[8] = {a0.x, a0.y, a0.z, a0.w, a1.x, a1.y, a1.z, a1.w};
                #pragma unroll
                for (int i = 0; i < 8; i++) {
                    u64 ad = dup2(a[i]);
                    acc[i][0] = ffma2(ad, wA.x, acc[i][0]);
                    acc[i][1] = ffma2(ad, wA.y, acc[i][1]);
                    acc[i][2] = ffma2(ad, wB.x, acc[i][2]);
                    acc[i][3] = ffma2(ad, wB.y, acc[i][3]);
                }
            }
            if (kt < 32) {
                wb4[(cur ^ 1) * 512 + tid] = r0;
                wb4[(cur ^ 1) * 512 + 256 + tid] = r1;
                __syncthreads();
            }
        }
    }
    __syncthreads();   // all featT reads done before overwriting with hiddenS

    // ---- Epilogue 1: bias + relu -> hiddenS[m][h] (row-major, reuse featT) ----
    float* hiddenS = featT;
    {
        const u64* b1p = reinterpret_cast<const u64*>(g_b1c);
        u64 bp[4];
        #pragma unroll
        for (int j = 0; j < 4; j++) bp[j] = b1p[hg * 4 + j];
        #pragma unroll
        for (int i = 0; i < 8; i++) {
            float2 v0 = unpack2(add2(acc[i][0], bp[0]));
            float2 v1 = unpack2(add2(acc[i][1], bp[1]));
            float2 v2 = unpack2(add2(acc[i][2], bp[2]));
            float2 v3 = unpack2(add2(acc[i][3], bp[3]));
            float4 o0, o1;
            o0.x = fmaxf(v0.x, 0.0f); o0.y = fmaxf(v0.y, 0.0f);
            o0.z = fmaxf(v1.x, 0.0f); o0.w = fmaxf(v1.y, 0.0f);
            o1.x = fmaxf(v2.x, 0.0f); o1.y = fmaxf(v2.y, 0.0f);
            o1.z = fmaxf(v3.x, 0.0f); o1.w = fmaxf(v3.y, 0.0f);
            float* dst = hiddenS + (mg * 8 + i) * 256 + hg * 8;
            *reinterpret_cast<float4*>(dst)     = o0;
            *reinterpret_cast<float4*>(dst + 4) = o1;
        }
    }
    __syncthreads();

    // ---- Stage 4: GEMM2  out[64][128] = hidden @ W2 + b2 ----
    const int og  = (wrp & 3) * 8 + (lane & 7);   // 0..31 (4 o-cols each)
    const int mg2 = (wrp >> 2) * 4 + (lane >> 3); // 0..7  (8 m-rows each)
    u64 acc2[8][2];
    #pragma unroll
    for (int i = 0; i < 8; i++) { acc2[i][0] = 0ULL; acc2[i][1] = 0ULL; }

    {
        const float4* w2g = reinterpret_cast<const float4*>(W2);  // [256][32] f4
        float4* wb4 = reinterpret_cast<float4*>(wbuf);
        float4 q = w2g[tid];          // tile 0: 8x128 = 256 f4
        wb4[tid] = q;
        __syncthreads();

        const float* hrow = hiddenS + mg2 * 8 * 256;
        for (int kt = 0; kt < 32; kt++) {
            const int cur = kt & 1;
            if (kt < 31) q = w2g[(kt + 1) * 256 + tid];
            const float* wrow = wbuf + cur * 1024 + og * 4;
            #pragma unroll
            for (int kk = 0; kk < 8; kk++) {
                const int k2 = kt * 8 + kk;
                ulonglong2 wv = *reinterpret_cast<const ulonglong2*>(wrow + kk * 128);
                #pragma unroll
                for (int i = 0; i < 8; i++) {
                    u64 hd = dup2(hrow[i * 256 + k2]);
                    acc2[i][0] = ffma2(hd, wv.x, acc2[i][0]);
                    acc2[i][1] = ffma2(hd, wv.y, acc2[i][1]);
                }
            }
            if (kt < 31) {
                wb4[(cur ^ 1) * 256 + tid] = q;
                __syncthreads();
            }
        }
    }

    // ---- Epilogue 2: + b2, store (128-bit packed stores) ----
    {
        ulonglong2 bb = *reinterpret_cast<const ulonglong2*>(b2 + og * 4);
        #pragma unroll
        for (int i = 0; i < 8; i++) {
            int row = rowbase + mg2 * 8 + i;
            ulonglong2 o;
            o.x = add2(acc2[i][0], bb.x);
            o.y = add2(acc2[i][1], bb.y);
            *reinterpret_cast<ulonglong2*>(out + (size_t)row * OUTD + og * 4) = o;
        }
    }
}

// ---------------------------------------------------------------------------
extern "C" void kernel_launch(void* const* d_in, const int* in_sizes, int n_in,
                              void* d_out, int out_size) {
    const float* poses = (const float*)d_in[0];
    const float* W1    = (const float*)d_in[1];
    const float* b1    = (const float*)d_in[2];
    const float* gamma = (const float*)d_in[3];
    const float* beta  = (const float*)d_in[4];
    const float* rmean = (const float*)d_in[5];
    const float* rvar  = (const float*)d_in[6];
    const float* W2    = (const float*)d_in[7];
    const float* b2    = (const float*)d_in[8];
    const float* jw    = (const float*)d_in[9];
    float* out = (float*)d_out;

    const int smem_bytes = (16896 + 4096 + 66 * PNS) * sizeof(float);  // 104296 B
    cudaFuncSetAttribute(fused_kernel, cudaFuncAttributeMaxDynamicSharedMemorySize,
                         smem_bytes);

    prep_kernel<<<KDIM, HID>>>(W1, b1, gamma, beta, rmean, rvar, jw);
    fused_kernel<<<(BB * SS) / TILE_M, NTHR, smem_bytes>>>(poses, W2, b2, out);
}

// round 11
// speedup vs baseline: 1.2551x; 1.2022x over previous
#include <cuda_runtime.h>
#include <cuda_bf16.h>
#include <math.h>
#include <stdint.h>
#include <stddef.h>

// Problem constants
#define BBATCH 64
#define SSEQ   2048
#define JJ     25
#define HID    256
#define OUTD   128
#define TM     128          // frames per CTA
#define NTHR   512
#define K1     272          // GEMM1 K (264 real + 8 pad)
#define CH1    17           // K1/16 chunks
#define CH2    16           // GEMM2 K chunks (256/16)
#define PNS    77

// smem strides (bytes) — chosen for conflict-free quad banking
#define FSB 560             // feat row stride   (280 bf16; 140 banks = 12 mod 32)
#define HSB 528             // hidden row stride (264 bf16; 132 banks = 4 mod 32)
#define WSB 40              // weight chunk row stride (20 bf16; 10 banks)

// smem layout (byte offsets)
#define OFF_WB 0
#define WBSTRIDE 20480      // per double-buffer slot: H plane @+0, L plane @+10240
#define OFF_FH 40960        // featH / hiddenH  (128*560 = 71680)
#define OFF_FL 112640       // featL / hiddenL
#define OFF_PN 184320       // pn: 130*77*4 = 40040
#define SMEM_TOTAL (184320 + 130 * PNS * 4)   // 224360

// Pre-split folded weights (written by prep each launch)
// W1: [17 chunks][256 n][20 k-slots] (slots 16..19 pad, never read)
__device__ __align__(16) __nv_bfloat16 g_W1H[CH1 * 256 * 20];
__device__ __align__(16) __nv_bfloat16 g_W1L[CH1 * 256 * 20];
// W2: [16 chunks][128 n][20 k-slots]
__device__ __align__(16) __nv_bfloat16 g_W2H[CH2 * 128 * 20];
__device__ __align__(16) __nv_bfloat16 g_W2L[CH2 * 128 * 20];
__device__ float g_b1c[HID];

__constant__ int c_conn[13][2] = {
    {0,1},{1,5},{1,6},{5,7},{7,9},{6,8},{8,10},
    {1,11},{1,12},{11,13},{13,15},{12,14},{14,16}};

// ======================= helpers ==========================================
__device__ __forceinline__ uint32_t smem_u32(const void* p) {
    uint32_t a;
    asm("{ .reg .u64 t; cvta.to.shared.u64 t, %1; cvt.u32.u64 %0, t; }" : "=r"(a) : "l"(p));
    return a;
}
__device__ __forceinline__ void cp16(uint32_t dst, const void* src) {
    asm volatile("cp.async.cg.shared.global [%0], [%1], 16;" :: "r"(dst), "l"(src));
}
#define CP_COMMIT() asm volatile("cp.async.commit_group;" ::: "memory")
#define CP_WAIT0()  asm volatile("cp.async.wait_group 0;" ::: "memory")

// HMMA m16n8k16 row.col f32.bf16.bf16.f32, D accumulates in place.
__device__ __forceinline__ void mma16816(float* d, const uint32_t* a, const uint32_t* b) {
    asm volatile(
        "mma.sync.aligned.m16n8k16.row.col.f32.bf16.bf16.f32 "
        "{%0,%1,%2,%3}, {%4,%5,%6,%7}, {%8,%9}, {%0,%1,%2,%3};"
        : "+f"(d[0]), "+f"(d[1]), "+f"(d[2]), "+f"(d[3])
        : "r"(a[0]), "r"(a[1]), "r"(a[2]), "r"(a[3]), "r"(b[0]), "r"(b[1]));
}

__device__ __forceinline__ void splitpack(float f0, float f1, uint32_t& hi, uint32_t& lo) {
    __nv_bfloat16 h0 = __float2bfloat16(f0);
    __nv_bfloat16 h1 = __float2bfloat16(f1);
    __nv_bfloat16 l0 = __float2bfloat16(f0 - __bfloat162float(h0));
    __nv_bfloat16 l1 = __float2bfloat16(f1 - __bfloat162float(h1));
    hi = (uint32_t)__bfloat16_as_ushort(h0) | ((uint32_t)__bfloat16_as_ushort(h1) << 16);
    lo = (uint32_t)__bfloat16_as_ushort(l0) | ((uint32_t)__bfloat16_as_ushort(l1) << 16);
}

// ======================= prep: fold + split + chunk weights ================
__global__ void prep_kernel(const float* __restrict__ W1, const float* __restrict__ b1,
                            const float* __restrict__ gamma, const float* __restrict__ beta,
                            const float* __restrict__ mean, const float* __restrict__ var,
                            const float* __restrict__ jw, const float* __restrict__ W2) {
    int t = threadIdx.x, blk = blockIdx.x;
    if (blk < K1) {
        int k = blk, h = t;          // t in [0,256)
        float g = gamma[h] * rsqrtf(var[h] + 1e-5f);
        float w = 0.0f;
        if (k < 264) {
            int korig, jidx;
            if (k < 225) { int sect = k / 75; int r = k % 75; jidx = r / 3; korig = jidx * 12 + sect * 3 + r % 3; }
            else         { int a = k - 225; jidx = a / 3; korig = jidx * 12 + 9 + a % 3; }
            w = W1[korig * HID + h] * g * jw[jidx];
        }
        __nv_bfloat16 hi = __float2bfloat16(w);
        __nv_bfloat16 lo = __float2bfloat16(w - __bfloat162float(hi));
        size_t idx = ((size_t)(k >> 4) * 256 + h) * 20 + (k & 15);
        g_W1H[idx] = hi;
        g_W1L[idx] = lo;
        if (k == 0) g_b1c[h] = (b1[h] - mean[h]) * g + beta[h];
    } else if (t < 128) {
        int k = blk - K1, n = t;     // k in [0,256)
        float w = W2[k * OUTD + n];
        __nv_bfloat16 hi = __float2bfloat16(w);
        __nv_bfloat16 lo = __float2bfloat16(w - __bfloat162float(hi));
        size_t idx = ((size_t)(k >> 4) * 128 + n) * 20 + (k & 15);
        g_W2H[idx] = hi;
        g_W2L[idx] = lo;
    }
}

// ======================= feature value ====================================
__device__ __forceinline__ float featval(int k, const float* P, const float* Pm1,
                                         const float* Pm2, bool has1, bool has2) {
    if (k < 75) return P[k];
    if (k < 150) { int i = k - 75; return has1 ? (P[i] - Pm1[i]) : 0.0f; }
    if (k < 225) {
        int i = k - 150;
        if (!has1) return 0.0f;
        float v = P[i] - Pm1[i];
        float vm1 = has2 ? (Pm1[i] - Pm2[i]) : 0.0f;
        return v - vm1;
    }
    if (k < 264) {
        int a = k - 225, c = a / 3, d = a % 3;
        int i0 = c_conn[c][0] * 3, i1 = c_conn[c][1] * 3;
        float vx = P[i1] - P[i0], vy = P[i1 + 1] - P[i0 + 1], vz = P[i1 + 2] - P[i0 + 2];
        float n = fmaxf(sqrtf(vx * vx + vy * vy + vz * vz), 1e-12f);
        float comp = (d == 0 ? vx : (d == 1 ? vy : vz)) / n;
        return acosf(fminf(fmaxf(comp, -1.0f), 1.0f));
    }
    return 0.0f;
}

// ======================= fused HMMA kernel =================================
__global__ void __launch_bounds__(NTHR, 1)
fused_kernel(const float* __restrict__ poses, const float* __restrict__ b2,
             float* __restrict__ out) {
    extern __shared__ char smem[];
    const uint32_t sb = smem_u32(smem);
    float* pn = (float*)(smem + OFF_PN);

    const int tid  = threadIdx.x;
    const int lane = tid & 31;
    const int wid  = tid >> 5;

    const int rowbase = blockIdx.x * TM;
    const int s0 = (blockIdx.x & 15) * TM;
    const int b  = blockIdx.x >> 4;

    // ---- prefetch W1 chunk0 while feature stages run ----
    for (int off = tid * 16; off < 10240; off += NTHR * 16) {
        cp16(sb + OFF_WB + off,         (const char*)g_W1H + off);
        cp16(sb + OFF_WB + 10240 + off, (const char*)g_W1L + off);
    }
    CP_COMMIT();

    // ---- Stage 1: normalize 130 frames (128 + 2 halo) ----
    if (tid < 130) {
        int s = s0 - 2 + tid;
        float* dst = pn + tid * PNS;
        if (s < 0) {
            for (int i = 0; i < 75; i++) dst[i] = 0.0f;
        } else {
            const float* src = poses + ((size_t)b * SSEQ + s) * (JJ * 3);
            float rx = src[0], ry = src[1], rz = src[2];
            float mx = 0.0f;
            for (int j = 0; j < JJ; j++) {
                float dx = src[j*3+0] - rx, dy = src[j*3+1] - ry, dz = src[j*3+2] - rz;
                dst[j*3+0] = dx; dst[j*3+1] = dy; dst[j*3+2] = dz;
                mx = fmaxf(mx, sqrtf(dx*dx + dy*dy + dz*dz));
            }
            float inv = 1.0f / (mx + 1e-8f);
            for (int i = 0; i < 75; i++) dst[i] *= inv;
        }
    }
    __syncthreads();

    // ---- Stage 2: features -> bf16 hi/lo smem planes ----
    {
        const int m  = tid >> 2;
        const int g4 = tid & 3;             // k-quarter: [g4*68, g4*68+68)
        const float* P   = pn + (m + 2) * PNS;
        const float* Pm1 = pn + (m + 1) * PNS;
        const float* Pm2 = pn + (m + 0) * PNS;
        const bool has1 = (s0 + m) >= 1, has2 = (s0 + m) >= 2;
        char* rowH = smem + OFF_FH + (size_t)m * FSB;
        char* rowL = smem + OFF_FL + (size_t)m * FSB;
        for (int j = 0; j < 34; j++) {
            int k = g4 * 68 + 2 * j;
            float f0 = featval(k,     P, Pm1, Pm2, has1, has2);
            float f1 = featval(k + 1, P, Pm1, Pm2, has1, has2);
            uint32_t H, L;
            splitpack(f0, f1, H, L);
            *(uint32_t*)(rowH + k * 2) = H;
            *(uint32_t*)(rowL + k * 2) = L;
        }
    }
    CP_WAIT0();
    __syncthreads();

    // ---- warp / lane geometry ----
    const int wm = wid >> 2;             // 0..3 -> m0 = wm*32
    const int wn = wid & 3;              // 0..3
    const int m0 = wm * 32;
    const int n0 = wn * 64;              // GEMM1 n-base
    const int qr = lane >> 2;            // row within m8/n8 group
    const int qk = (lane & 3) * 2;       // k (or n) pair offset

    // ======== GEMM1: hidden[128][256] = feat[128][272] @ W1c ========
    float acc[2][8][4];
    #pragma unroll
    for (int g = 0; g < 2; g++)
        #pragma unroll
        for (int nt = 0; nt < 8; nt++)
            #pragma unroll
            for (int q = 0; q < 4; q++) acc[g][nt][q] = 0.0f;

    for (int kt = 0; kt < CH1; kt++) {
        if (kt < CH1 - 1) {              // prefetch next chunk
            const char* srcH = (const char*)g_W1H + (size_t)(kt + 1) * 10240;
            const char* srcL = (const char*)g_W1L + (size_t)(kt + 1) * 10240;
            uint32_t db = sb + OFF_WB + ((kt + 1) & 1) * WBSTRIDE;
            for (int off = tid * 16; off < 10240; off += NTHR * 16) {
                cp16(db + off, srcH + off);
                cp16(db + 10240 + off, srcL + off);
            }
            CP_COMMIT();
        }
        // A fragments (hi & lo) for two m16 groups
        uint32_t aH[2][4], aL[2][4];
        {
            const char* baseH = smem + OFF_FH + (kt * 16 + qk) * 2;
            const char* baseL = smem + OFF_FL + (kt * 16 + qk) * 2;
            #pragma unroll
            for (int g = 0; g < 2; g++) {
                int r = m0 + g * 16 + qr;
                const char* pH = baseH + (size_t)r * FSB;
                const char* pL = baseL + (size_t)r * FSB;
                aH[g][0] = *(const uint32_t*)(pH);
                aH[g][1] = *(const uint32_t*)(pH + 8 * FSB);
                aH[g][2] = *(const uint32_t*)(pH + 16);
                aH[g][3] = *(const uint32_t*)(pH + 8 * FSB + 16);
                aL[g][0] = *(const uint32_t*)(pL);
                aL[g][1] = *(const uint32_t*)(pL + 8 * FSB);
                aL[g][2] = *(const uint32_t*)(pL + 16);
                aL[g][3] = *(const uint32_t*)(pL + 8 * FSB + 16);
            }
        }
        const char* wbH = smem + OFF_WB + (kt & 1) * WBSTRIDE;
        const char* wbL = wbH + 10240;
        #pragma unroll
        for (int nt = 0; nt < 8; nt++) {
            int n = n0 + nt * 8 + qr;
            const char* pH = wbH + n * WSB + (lane & 3) * 4;
            const char* pL = wbL + n * WSB + (lane & 3) * 4;
            uint32_t bH[2] = { *(const uint32_t*)pH, *(const uint32_t*)(pH + 16) };
            uint32_t bL[2] = { *(const uint32_t*)pL, *(const uint32_t*)(pL + 16) };
            mma16816(acc[0][nt], aH[0], bH);
            mma16816(acc[1][nt], aH[1], bH);
            mma16816(acc[0][nt], aH[0], bL);
            mma16816(acc[1][nt], aH[1], bL);
            mma16816(acc[0][nt], aL[0], bH);
            mma16816(acc[1][nt], aL[1], bH);
        }
        if (kt < CH1 - 1) CP_WAIT0();
        __syncthreads();
    }

    // ---- prefetch W2 chunk0, then epilogue1: bias+relu+split -> hidden smem ----
    for (int off = tid * 16; off < 5120; off += NTHR * 16) {
        cp16(sb + OFF_WB + off,         (const char*)g_W2H + off);
        cp16(sb + OFF_WB + 10240 + off, (const char*)g_W2L + off);
    }
    CP_COMMIT();

    #pragma unroll
    for (int g = 0; g < 2; g++) {
        int r = m0 + g * 16 + qr;
        char* rH0 = smem + OFF_FH + (size_t)r * HSB;
        char* rL0 = smem + OFF_FL + (size_t)r * HSB;
        #pragma unroll
        for (int nt = 0; nt < 8; nt++) {
            int c = n0 + nt * 8 + qk;
            float bb0 = g_b1c[c], bb1 = g_b1c[c + 1];
            float h0 = fmaxf(acc[g][nt][0] + bb0, 0.0f);
            float h1 = fmaxf(acc[g][nt][1] + bb1, 0.0f);
            float h2 = fmaxf(acc[g][nt][2] + bb0, 0.0f);
            float h3 = fmaxf(acc[g][nt][3] + bb1, 0.0f);
            uint32_t H, L;
            splitpack(h0, h1, H, L);
            *(uint32_t*)(rH0 + c * 2) = H;
            *(uint32_t*)(rL0 + c * 2) = L;
            splitpack(h2, h3, H, L);
            *(uint32_t*)(rH0 + 8 * HSB + c * 2) = H;
            *(uint32_t*)(rL0 + 8 * HSB + c * 2) = L;
        }
    }
    CP_WAIT0();
    __syncthreads();

    // ======== GEMM2: out[128][128] = hidden[128][256] @ W2 ========
    const int n02 = wn * 32;
    float acc2[2][4][4];
    #pragma unroll
    for (int g = 0; g < 2; g++)
        #pragma unroll
        for (int nt = 0; nt < 4; nt++)
            #pragma unroll
            for (int q = 0; q < 4; q++) acc2[g][nt][q] = 0.0f;

    for (int kt = 0; kt < CH2; kt++) {
        if (kt < CH2 - 1) {
            const char* srcH = (const char*)g_W2H + (size_t)(kt + 1) * 5120;
            const char* srcL = (const char*)g_W2L + (size_t)(kt + 1) * 5120;
            uint32_t db = sb + OFF_WB + ((kt + 1) & 1) * WBSTRIDE;
            for (int off = tid * 16; off < 5120; off += NTHR * 16) {
                cp16(db + off, srcH + off);
                cp16(db + 10240 + off, srcL + off);
            }
            CP_COMMIT();
        }
        uint32_t aH[2][4], aL[2][4];
        {
            const char* baseH = smem + OFF_FH + (kt * 16 + qk) * 2;
            const char* baseL = smem + OFF_FL + (kt * 16 + qk) * 2;
            #pragma unroll
            for (int g = 0; g < 2; g++) {
                int r = m0 + g * 16 + qr;
                const char* pH = baseH + (size_t)r * HSB;
                const char* pL = baseL + (size_t)r * HSB;
                aH[g][0] = *(const uint32_t*)(pH);
                aH[g][1] = *(const uint32_t*)(pH + 8 * HSB);
                aH[g][2] = *(const uint32_t*)(pH + 16);
                aH[g][3] = *(const uint32_t*)(pH + 8 * HSB + 16);
                aL[g][0] = *(const uint32_t*)(pL);
                aL[g][1] = *(const uint32_t*)(pL + 8 * HSB);
                aL[g][2] = *(const uint32_t*)(pL + 16);
                aL[g][3] = *(const uint32_t*)(pL + 8 * HSB + 16);
            }
        }
        const char* wbH = smem + OFF_WB + (kt & 1) * WBSTRIDE;
        const char* wbL = wbH + 10240;
        #pragma unroll
        for (int nt = 0; nt < 4; nt++) {
            int n = n02 + nt * 8 + qr;
            const char* pH = wbH + n * WSB + (lane & 3) * 4;
            const char* pL = wbL + n * WSB + (lane & 3) * 4;
            uint32_t bH[2] = { *(const uint32_t*)pH, *(const uint32_t*)(pH + 16) };
            uint32_t bL[2] = { *(const uint32_t*)pL, *(const uint32_t*)(pL + 16) };
            mma16816(acc2[0][nt], aH[0], bH);
            mma16816(acc2[1][nt], aH[1], bH);
            mma16816(acc2[0][nt], aH[0], bL);
            mma16816(acc2[1][nt], aH[1], bL);
            mma16816(acc2[0][nt], aL[0], bH);
            mma16816(acc2[1][nt], aL[1], bH);
        }
        if (kt < CH2 - 1) CP_WAIT0();
        __syncthreads();
    }

    // ---- Epilogue 2: + b2, store ----
    #pragma unroll
    for (int g = 0; g < 2; g++) {
        int r = m0 + g * 16 + qr;
        float* o0 = out + (size_t)(rowbase + r) * OUTD;
        float* o1 = out + (size_t)(rowbase + r + 8) * OUTD;
        #pragma unroll
        for (int nt = 0; nt < 4; nt++) {
            int c = n02 + nt * 8 + qk;
            float b20 = b2[c], b21 = b2[c + 1];
            float2 v0, v1;
            v0.x = acc2[g][nt][0] + b20; v0.y = acc2[g][nt][1] + b21;
            v1.x = acc2[g][nt][2] + b20; v1.y = acc2[g][nt][3] + b21;
            *reinterpret_cast<float2*>(o0 + c) = v0;
            *reinterpret_cast<float2*>(o1 + c) = v1;
        }
    }
}

// ---------------------------------------------------------------------------
extern "C" void kernel_launch(void* const* d_in, const int* in_sizes, int n_in,
                              void* d_out, int out_size) {
    const float* poses = (const float*)d_in[0];
    const float* W1    = (const float*)d_in[1];
    const float* b1    = (const float*)d_in[2];
    const float* gamma = (const float*)d_in[3];
    const float* beta  = (const float*)d_in[4];
    const float* rmean = (const float*)d_in[5];
    const float* rvar  = (const float*)d_in[6];
    const float* W2    = (const float*)d_in[7];
    const float* b2    = (const float*)d_in[8];
    const float* jw    = (const float*)d_in[9];
    float* out = (float*)d_out;

    cudaFuncSetAttribute(fused_kernel, cudaFuncAttributeMaxDynamicSharedMemorySize,
                         SMEM_TOTAL);

    prep_kernel<<<K1 + 256, 256>>>(W1, b1, gamma, beta, rmean, rvar, jw, W2);
    fused_kernel<<<(BBATCH * SSEQ) / TM, NTHR, SMEM_TOTAL>>>(poses, b2, out);
}

// round 13
// speedup vs baseline: 1.6178x; 1.2890x over previous
#include <cuda_runtime.h>
#include <cuda_bf16.h>
#include <math.h>
#include <stdint.h>
#include <stddef.h>

// Problem constants
#define BBATCH 64
#define SSEQ   2048
#define JJ     25
#define HID    256
#define OUTD   128
#define TM     128          // frames per CTA
#define NTHR   512
#define K1     272          // GEMM1 K (264 real + 8 pad)
#define CH1    17           // K1/16 chunks
#define CH2    16           // GEMM2 K chunks (256/16)
#define PNS    77

// smem strides (bytes)
#define FSB 560             // feat row stride   (272 bf16 = 544B + pad) -> banks 12 mod 32
#define HSB 528             // hidden row stride (256 bf16 = 512B + pad) -> banks 4 mod 32

// Weight chunk sizes (pre-fragmented: [n8 group][lane 32][16B = bH0,bH1,bL0,bL1])
#define W1CHB 16384         // 32 n8-groups * 32 lanes * 16B
#define W2CHB 8192          // 16 n8-groups * 32 lanes * 16B

// smem layout (byte offsets)
#define MB_POSE 0
#define MB_W0   8
#define MB_W1   16
#define REG0    64                       // raw pose slab / weight double-buffer (39040)
#define WBUF0   REG0
#define WBUF1   (REG0 + W1CHB)
#define OFF_FH  (REG0 + 39040)           // 39104
#define OFF_FL  (OFF_FH + 71680)         // 110784 (128*560)
#define OFF_PN  (OFF_FL + 71680)         // 182464
#define SMEM_TOTAL (OFF_PN + 130 * PNS * 4)   // 222504

#define POSES_BYTES ((size_t)BBATCH * SSEQ * JJ * 3 * 4)

// Pre-fragmented folded weights (written by prep each launch)
__device__ __align__(16) unsigned char g_W1F[CH1 * W1CHB];   // 278528 B
__device__ __align__(16) unsigned char g_W2F[CH2 * W2CHB];   // 131072 B
__device__ float g_b1c[HID];

__constant__ int c_conn[13][2] = {
    {0,1},{1,5},{1,6},{5,7},{7,9},{6,8},{8,10},
    {1,11},{1,12},{11,13},{13,15},{12,14},{14,16}};

// ======================= helpers ==========================================
__device__ __forceinline__ uint32_t smem_u32(const void* p) {
    uint32_t a;
    asm("{ .reg .u64 t; cvta.to.shared.u64 t, %1; cvt.u32.u64 %0, t; }" : "=r"(a) : "l"(p));
    return a;
}
#define MBAR_INIT(mb, n) asm volatile("mbarrier.init.shared.b64 [%0], %1;" :: "r"(mb), "r"(n) : "memory")
#define MBAR_EXPECT(mb, bytes) asm volatile("mbarrier.arrive.expect_tx.shared.b64 _, [%0], %1;" :: "r"(mb), "r"(bytes) : "memory")
#define MBAR_WAIT(mb, par) do {                                              \
    uint32_t _mb = (mb), _p = (par), _d;                                     \
    asm volatile("{ .reg .pred p; mbarrier.try_wait.parity.acquire.cta.shared::cta.b64 p, [%1], %2; selp.b32 %0,1,0,p; }" \
        : "=r"(_d) : "r"(_mb), "r"(_p) : "memory");                          \
    if (!_d) {                                                               \
        asm volatile("{ .reg .pred P1; WL_%=: mbarrier.try_wait.parity.acquire.cta.shared::cta.b64 P1, [%0], %1, 0x989680;" \
            " @P1 bra.uni WD_%=; bra.uni WL_%=; WD_%=: }"                    \
            :: "r"(_mb), "r"(_p) : "memory");                                \
    } } while (0)

__device__ __forceinline__ void bulk_g2s(uint32_t dst, const void* gsrc, uint32_t bytes, uint32_t mb) {
    uint64_t g = (uint64_t)__cvta_generic_to_global(gsrc);
    asm volatile("cp.async.bulk.shared::cluster.global.mbarrier::complete_tx::bytes [%0], [%1], %2, [%3];"
        :: "r"(dst), "l"(g), "r"(bytes), "r"(mb) : "memory");
}

__device__ __forceinline__ void ldm_x4(uint32_t* r, uint32_t saddr) {
    asm volatile("ldmatrix.sync.aligned.m8n8.x4.shared.b16 {%0,%1,%2,%3}, [%4];"
        : "=r"(r[0]), "=r"(r[1]), "=r"(r[2]), "=r"(r[3]) : "r"(saddr));
}

// HMMA m16n8k16 row.col f32.bf16.bf16.f32, D accumulates in place.
__device__ __forceinline__ void mma16816(float* d, const uint32_t* a, uint32_t b0, uint32_t b1) {
    asm volatile(
        "mma.sync.aligned.m16n8k16.row.col.f32.bf16.bf16.f32 "
        "{%0,%1,%2,%3}, {%4,%5,%6,%7}, {%8,%9}, {%0,%1,%2,%3};"
        : "+f"(d[0]), "+f"(d[1]), "+f"(d[2]), "+f"(d[3])
        : "r"(a[0]), "r"(a[1]), "r"(a[2]), "r"(a[3]), "r"(b0), "r"(b1));
}

__device__ __forceinline__ void splitpack(float f0, float f1, uint32_t& hi, uint32_t& lo) {
    __nv_bfloat16 h0 = __float2bfloat16(f0);
    __nv_bfloat16 h1 = __float2bfloat16(f1);
    __nv_bfloat16 l0 = __float2bfloat16(f0 - __bfloat162float(h0));
    __nv_bfloat16 l1 = __float2bfloat16(f1 - __bfloat162float(h1));
    hi = (uint32_t)__bfloat16_as_ushort(h0) | ((uint32_t)__bfloat16_as_ushort(h1) << 16);
    lo = (uint32_t)__bfloat16_as_ushort(l0) | ((uint32_t)__bfloat16_as_ushort(l1) << 16);
}

// ======================= prep: fold + split + fragment weights =============
__global__ void prep_kernel(const float* __restrict__ W1, const float* __restrict__ b1,
                            const float* __restrict__ gamma, const float* __restrict__ beta,
                            const float* __restrict__ mean, const float* __restrict__ var,
                            const float* __restrict__ jw, const float* __restrict__ W2) {
    int t = threadIdx.x, blk = blockIdx.x;
    if (blk < K1) {
        int k = blk, h = t;          // t in [0,256)
        float g = gamma[h] * rsqrtf(var[h] + 1e-5f);
        float w = 0.0f;
        if (k < 264) {
            int korig, jidx;
            if (k < 225) { int sect = k / 75; int r = k % 75; jidx = r / 3; korig = jidx * 12 + sect * 3 + r % 3; }
            else         { int a = k - 225; jidx = a / 3; korig = jidx * 12 + 9 + a % 3; }
            w = W1[korig * HID + h] * g * jw[jidx];
        }
        __nv_bfloat16 hi = __float2bfloat16(w);
        __nv_bfloat16 lo = __float2bfloat16(w - __bfloat162float(hi));
        int chunk = k >> 4, kc = k & 15, n8 = h >> 3, qr = h & 7;
        int lane = qr * 4 + ((kc & 7) >> 1);
        int boff = (kc >> 3) * 4 + (kc & 1) * 2;
        size_t idx = (((size_t)chunk * 32 + n8) * 32 + lane) * 16 + boff;
        *(__nv_bfloat16*)(g_W1F + idx)     = hi;
        *(__nv_bfloat16*)(g_W1F + idx + 8) = lo;
        if (k == 0) g_b1c[h] = (b1[h] - mean[h]) * g + beta[h];
    } else if (t < 128) {
        int k = blk - K1, n = t;     // k in [0,256)
        float w = W2[k * OUTD + n];
        __nv_bfloat16 hi = __float2bfloat16(w);
        __nv_bfloat16 lo = __float2bfloat16(w - __bfloat162float(hi));
        int chunk = k >> 4, kc = k & 15, n8 = n >> 3, qr = n & 7;
        int lane = qr * 4 + ((kc & 7) >> 1);
        int boff = (kc >> 3) * 4 + (kc & 1) * 2;
        size_t idx = (((size_t)chunk * 16 + n8) * 32 + lane) * 16 + boff;
        *(__nv_bfloat16*)(g_W2F + idx)     = hi;
        *(__nv_bfloat16*)(g_W2F + idx + 8) = lo;
    }
}

// ======================= feature value ====================================
__device__ __forceinline__ float featval(int k, const float* P, const float* Pm1,
                                         const float* Pm2, bool has1, bool has2) {
    if (k < 75) return P[k];
    if (k < 150) { int i = k - 75; return has1 ? (P[i] - Pm1[i]) : 0.0f; }
    if (k < 225) {
        int i = k - 150;
        if (!has1) return 0.0f;
        float v = P[i] - Pm1[i];
        float vm1 = has2 ? (Pm1[i] - Pm2[i]) : 0.0f;
        return v - vm1;
    }
    if (k < 264) {
        int a = k - 225, c = a / 3, d = a % 3;
        int i0 = c_conn[c][0] * 3, i1 = c_conn[c][1] * 3;
        float vx = P[i1] - P[i0], vy = P[i1 + 1] - P[i0 + 1], vz = P[i1 + 2] - P[i0 + 2];
        float n = fmaxf(sqrtf(vx * vx + vy * vy + vz * vz), 1e-12f);
        float comp = (d == 0 ? vx : (d == 1 ? vy : vz)) / n;
        return acosf(fminf(fmaxf(comp, -1.0f), 1.0f));
    }
    return 0.0f;
}

// ======================= fused HMMA kernel =================================
__global__ void __launch_bounds__(NTHR, 1)
fused_kernel(const float* __restrict__ poses, const float* __restrict__ b2,
             float* __restrict__ out) {
    extern __shared__ char smem[];
    const uint32_t sb = smem_u32(smem);
    float* pn = (float*)(smem + OFF_PN);

    const int tid  = threadIdx.x;
    const int lane = tid & 31;
    const int wid  = tid >> 5;

    const int rowbase = blockIdx.x * TM;
    const int s0 = (blockIdx.x & 15) * TM;
    const int b  = blockIdx.x >> 4;

    // ---- init barriers + bulk-load pose slab into REG0 ----
    const int s_start = (s0 >= 2) ? (s0 - 2) : 0;
    const int nrows = 130 - (s0 == 0 ? 2 : 0);
    size_t base_bytes = ((size_t)b * SSEQ + s_start) * 300;
    size_t aligned = base_bytes & ~(size_t)15;
    const int delta = (int)(base_bytes - aligned);
    if (tid == 0) {
        MBAR_INIT(sb + MB_POSE, 1);
        MBAR_INIT(sb + MB_W0, 1);
        MBAR_INIT(sb + MB_W1, 1);
        size_t want = (size_t)((nrows * 300 + delta + 15) & ~15);
        size_t avail = POSES_BYTES - aligned;             // clamp: never read OOB
        uint32_t csz = (uint32_t)(want <= avail ? want : (avail & ~(size_t)15));
        MBAR_EXPECT(sb + MB_POSE, csz);
        bulk_g2s(sb + REG0, (const char*)poses + aligned, csz, sb + MB_POSE);
    }
    __syncthreads();
    MBAR_WAIT(sb + MB_POSE, 0);

    // ---- Stage 1: normalize 130 frames (128 + 2 halo) from smem slab ----
    if (tid < 130) {
        int s = s0 - 2 + tid;
        float* dst = pn + tid * PNS;
        if (s < 0) {
            for (int i = 0; i < 75; i++) dst[i] = 0.0f;
        } else {
            const float* src = (const float*)(smem + REG0) + (delta >> 2) + (s - s_start) * 75;
            float rx = src[0], ry = src[1], rz = src[2];
            float mx = 0.0f;
            for (int j = 0; j < JJ; j++) {
                float dx = src[j*3+0] - rx, dy = src[j*3+1] - ry, dz = src[j*3+2] - rz;
                dst[j*3+0] = dx; dst[j*3+1] = dy; dst[j*3+2] = dz;
                mx = fmaxf(mx, sqrtf(dx*dx + dy*dy + dz*dz));
            }
            float inv = 1.0f / (mx + 1e-8f);
            for (int i = 0; i < 75; i++) dst[i] *= inv;
        }
    }
    __syncthreads();   // raw slab dead; weight buffers may now overwrite it

    // ---- kick W1 chunk 0 & 1 bulk loads (overlap with stage 2) ----
    if (tid == 0) {
        MBAR_EXPECT(sb + MB_W0, W1CHB);
        bulk_g2s(sb + WBUF0, g_W1F, W1CHB, sb + MB_W0);
        MBAR_EXPECT(sb + MB_W1, W1CHB);
        bulk_g2s(sb + WBUF1, g_W1F + W1CHB, W1CHB, sb + MB_W1);
    }

    // ---- Stage 2: features -> bf16 hi/lo smem planes ----
    {
        const int m  = tid >> 2;
        const int g4 = tid & 3;
        const float* P   = pn + (m + 2) * PNS;
        const float* Pm1 = pn + (m + 1) * PNS;
        const float* Pm2 = pn + (m + 0) * PNS;
        const bool has1 = (s0 + m) >= 1, has2 = (s0 + m) >= 2;
        char* rowH = smem + OFF_FH + (size_t)m * FSB;
        char* rowL = smem + OFF_FL + (size_t)m * FSB;
        for (int j = 0; j < 34; j++) {
            int k = g4 * 68 + 2 * j;
            float f0 = featval(k,     P, Pm1, Pm2, has1, has2);
            float f1 = featval(k + 1, P, Pm1, Pm2, has1, has2);
            uint32_t H, L;
            splitpack(f0, f1, H, L);
            *(uint32_t*)(rowH + k * 2) = H;
            *(uint32_t*)(rowL + k * 2) = L;
        }
    }
    __syncthreads();

    // ---- warp / lane geometry ----
    const int wm = wid >> 2;             // 0..3 -> m0 = wm*32
    const int wn = wid & 3;              // 0..3
    const int m0 = wm * 32;
    const int n0 = wn * 64;              // GEMM1 n-base
    const int qr = lane >> 2;
    const int qk = (lane & 3) * 2;

    // ldmatrix lane address components (row & k-segment from lane id)
    const int lrow = ((lane >> 3) & 1) * 8 + (lane & 7);
    const int lkof = (lane >> 4) * 8;

    int ph0 = 0, ph1 = 0;                // consumer phase per weight slot

    // ======== GEMM1: hidden[128][256] = feat[128][272] @ W1c ========
    float acc[2][8][4];
    #pragma unroll
    for (int g = 0; g < 2; g++)
        #pragma unroll
        for (int nt = 0; nt < 8; nt++)
            #pragma unroll
            for (int q = 0; q < 4; q++) acc[g][nt][q] = 0.0f;

    for (int kt = 0; kt < CH1; kt++) {
        const int slot = kt & 1;
        if (slot == 0) { MBAR_WAIT(sb + MB_W0, ph0); ph0 ^= 1; }
        else           { MBAR_WAIT(sb + MB_W1, ph1); ph1 ^= 1; }

        // A fragments via ldmatrix.x4 (H & L planes, two m16 groups)
        uint32_t aH[2][4], aL[2][4];
        {
            uint32_t kb = (uint32_t)(kt * 16 + lkof) * 2;
            #pragma unroll
            for (int g = 0; g < 2; g++) {
                uint32_t r = (uint32_t)(m0 + g * 16 + lrow);
                ldm_x4(aH[g], sb + OFF_FH + r * FSB + kb);
                ldm_x4(aL[g], sb + OFF_FL + r * FSB + kb);
            }
        }
        const char* wb = smem + (slot ? WBUF1 : WBUF0);
        #pragma unroll
        for (int nt = 0; nt < 8; nt++) {
            uint4 bv = *(const uint4*)(wb + ((wn * 8 + nt) * 32 + lane) * 16);
            mma16816(acc[0][nt], aH[0], bv.x, bv.y);
            mma16816(acc[1][nt], aH[1], bv.x, bv.y);
            mma16816(acc[0][nt], aH[0], bv.z, bv.w);
            mma16816(acc[1][nt], aH[1], bv.z, bv.w);
            mma16816(acc[0][nt], aL[0], bv.x, bv.y);
            mma16816(acc[1][nt], aL[1], bv.x, bv.y);
        }
        __syncthreads();                 // all reads of this slot done
        if (tid == 0 && kt + 2 < CH1) {  // refill this slot with chunk kt+2
            uint32_t mb = sb + (slot ? MB_W1 : MB_W0);
            MBAR_EXPECT(mb, W1CHB);
            bulk_g2s(sb + (slot ? WBUF1 : WBUF0), g_W1F + (size_t)(kt + 2) * W1CHB, W1CHB, mb);
        }
    }

    // ---- kick W2 chunk 0 & 1 (slots are idle now) ----
    if (tid == 0) {
        MBAR_EXPECT(sb + MB_W0, W2CHB);
        bulk_g2s(sb + WBUF0, g_W2F, W2CHB, sb + MB_W0);
        MBAR_EXPECT(sb + MB_W1, W2CHB);
        bulk_g2s(sb + WBUF1, g_W2F + W2CHB, W2CHB, sb + MB_W1);
    }

    // ---- Epilogue 1: bias + relu + split -> hidden smem (overwrites feat) ----
    #pragma unroll
    for (int g = 0; g < 2; g++) {
        int r = m0 + g * 16 + qr;
        char* rH0 = smem + OFF_FH + (size_t)r * HSB;
        char* rL0 = smem + OFF_FL + (size_t)r * HSB;
        #pragma unroll
        for (int nt = 0; nt < 8; nt++) {
            int c = n0 + nt * 8 + qk;
            float bb0 = g_b1c[c], bb1 = g_b1c[c + 1];
            float h0 = fmaxf(acc[g][nt][0] + bb0, 0.0f);
            float h1 = fmaxf(acc[g][nt][1] + bb1, 0.0f);
            float h2 = fmaxf(acc[g][nt][2] + bb0, 0.0f);
            float h3 = fmaxf(acc[g][nt][3] + bb1, 0.0f);
            uint32_t H, L;
            splitpack(h0, h1, H, L);
            *(uint32_t*)(rH0 + c * 2) = H;
            *(uint32_t*)(rL0 + c * 2) = L;
            splitpack(h2, h3, H, L);
            *(uint32_t*)(rH0 + 8 * HSB + c * 2) = H;
            *(uint32_t*)(rL0 + 8 * HSB + c * 2) = L;
        }
    }
    __syncthreads();

    // ======== GEMM2: out[128][128] = hidden[128][256] @ W2 ========
    const int n02 = wn * 32;
    float acc2[2][4][4];
    #pragma unroll
    for (int g = 0; g < 2; g++)
        #pragma unroll
        for (int nt = 0; nt < 4; nt++)
            #pragma unroll
            for (int q = 0; q < 4; q++) acc2[g][nt][q] = 0.0f;

    for (int kt = 0; kt < CH2; kt++) {
        const int slot = kt & 1;
        if (slot == 0) { MBAR_WAIT(sb + MB_W0, ph0); ph0 ^= 1; }
        else           { MBAR_WAIT(sb + MB_W1, ph1); ph1 ^= 1; }

        uint32_t aH[2][4], aL[2][4];
        {
            uint32_t kb = (uint32_t)(kt * 16 + lkof) * 2;
            #pragma unroll
            for (int g = 0; g < 2; g++) {
                uint32_t r = (uint32_t)(m0 + g * 16 + lrow);
                ldm_x4(aH[g], sb + OFF_FH + r * HSB + kb);
                ldm_x4(aL[g], sb + OFF_FL + r * HSB + kb);
            }
        }
        const char* wb = smem + (slot ? WBUF1 : WBUF0);
        #pragma unroll
        for (int nt = 0; nt < 4; nt++) {
            uint4 bv = *(const uint4*)(wb + ((wn * 4 + nt) * 32 + lane) * 16);
            mma16816(acc2[0][nt], aH[0], bv.x, bv.y);
            mma16816(acc2[1][nt], aH[1], bv.x, bv.y);
            mma16816(acc2[0][nt], aH[0], bv.z, bv.w);
            mma16816(acc2[1][nt], aH[1], bv.z, bv.w);
            mma16816(acc2[0][nt], aL[0], bv.x, bv.y);
            mma16816(acc2[1][nt], aL[1], bv.x, bv.y);
        }
        __syncthreads();
        if (tid == 0 && kt + 2 < CH2) {
            uint32_t mb = sb + (slot ? MB_W1 : MB_W0);
            MBAR_EXPECT(mb, W2CHB);
            bulk_g2s(sb + (slot ? WBUF1 : WBUF0), g_W2F + (size_t)(kt + 2) * W2CHB, W2CHB, mb);
        }
    }

    // ---- Epilogue 2: + b2, store (FIXED: use acc2[g], not acc2[0]) ----
    #pragma unroll
    for (int g = 0; g < 2; g++) {
        int r = m0 + g * 16 + qr;
        float* o0 = out + (size_t)(rowbase + r) * OUTD;
        float* o1 = out + (size_t)(rowbase + r + 8) * OUTD;
        #pragma unroll
        for (int nt = 0; nt < 4; nt++) {
            int c = n02 + nt * 8 + qk;
            float b20 = b2[c], b21 = b2[c + 1];
            float2 v0, v1;
            v0.x = acc2[g][nt][0] + b20; v0.y = acc2[g][nt][1] + b21;
            v1.x = acc2[g][nt][2] + b20; v1.y = acc2[g][nt][3] + b21;
            *reinterpret_cast<float2*>(o0 + c) = v0;
            *reinterpret_cast<float2*>(o1 + c) = v1;
        }
    }
}

// ---------------------------------------------------------------------------
extern "C" void kernel_launch(void* const* d_in, const int* in_sizes, int n_in,
                              void* d_out, int out_size) {
    const float* poses = (const float*)d_in[0];
    const float* W1    = (const float*)d_in[1];
    const float* b1    = (const float*)d_in[2];
    const float* gamma = (const float*)d_in[3];
    const float* beta  = (const float*)d_in[4];
    const float* rmean = (const float*)d_in[5];
    const float* rvar  = (const float*)d_in[6];
    const float* W2    = (const float*)d_in[7];
    const float* b2    = (const float*)d_in[8];
    const float* jw    = (const float*)d_in[9];
    float* out = (float*)d_out;

    cudaFuncSetAttribute(fused_kernel, cudaFuncAttributeMaxDynamicSharedMemorySize,
                         SMEM_TOTAL);

    prep_kernel<<<K1 + 256, 256>>>(W1, b1, gamma, beta, rmean, rvar, jw, W2);
    fused_kernel<<<(BBATCH * SSEQ) / TM, NTHR, SMEM_TOTAL>>>(poses, b2, out);
}